// round 3
// baseline (speedup 1.0000x reference)
#include <cuda_runtime.h>
#include <cstdint>

// Problem constants
#define NB 16        // batch
#define BB 288       // input capsules
#define NC 32        // output capsules (softmax dim)
#define NP 16        // pose dim
#define NF 36        // f*f positions
#define NFH 18       // f-half
#define FSPLIT 2
#define NCHUNK 9     // B chunks
#define BCH 32       // B per chunk
#define SLICE (NC*NP*NF)      // 18432
#define SLICE_H (NC*NP*NFH)   // 9216
#define CF (NC*NF)            // 1152
#define CFH (NC*NFH)          // 576
#define THREADS 256
#define NLD (SLICE_H/2/THREADS)  // 18 float2 per thread
#define EPS 1e-5f

// ---------------- device scratch ----------------
__device__ float g_asm[NB*BB*NF];            // softmax_B(a)
__device__ float g_Spart[NB*NCHUNK*SLICE];   // per-chunk partial S
__device__ float g_S[NB*SLICE];              // reduced S
__device__ float g_w[NB*SLICE];              // running sum of v
__device__ float g_s[NB*CF];                 // 1/(mx-mn)
__device__ int   g_mx[NB*CF];
__device__ int   g_mn[NB*CF];

// ---------------- init ----------------
__global__ void init_kernel() {
    int g = blockIdx.x * blockDim.x + threadIdx.x;
    if (g < NB*CF) { g_mx[g] = 0; g_mn[g] = 0x7F800000; }
}

// ---------------- softmax of a over B, per (b,f) ----------------
__global__ void asm_kernel(const float* __restrict__ a) {
    __shared__ float red[BB];
    int bf = blockIdx.x;
    int bi = bf / NF, f = bf - bi*NF;
    int t = threadIdx.x;
    float x = a[(bi*BB + t)*NF + f];
    red[t] = x; __syncthreads();
    for (int st = 256; st >= 1; st >>= 1) {
        if (t < st && t + st < BB) red[t] = fmaxf(red[t], red[t + st]);
        __syncthreads();
    }
    float m = red[0]; __syncthreads();
    float e = __expf(x - m);
    red[t] = e; __syncthreads();
    for (int st = 256; st >= 1; st >>= 1) {
        if (t < st && t + st < BB) red[t] += red[t + st];
        __syncthreads();
    }
    g_asm[(bi*BB + t)*NF + f] = e / red[0];
}

// ---------------- pass 0: norms -> min/max, S0 = sum_B c0*u ----------------
__global__ __launch_bounds__(THREADS, 2)
void pass0_kernel(const float* __restrict__ u) {
    extern __shared__ float sh[];
    float* u_sm  = sh;                 // SLICE_H
    float* bmax  = sh + SLICE_H;       // CFH
    float* bmin  = bmax + CFH;         // CFH
    float* a_row = bmin + CFH;         // 32 (18 used)

    int bid = blockIdx.x;
    int fh = bid & 1;
    int ch = (bid >> 1) % NCHUNK;
    int bi = bid / (NCHUNK*FSPLIT);
    int tid = threadIdx.x;

    // per-thread float2 offsets into the global f-split layout (constant over B)
    int off2[NLD];
    #pragma unroll
    for (int k = 0; k < NLD; k++) {
        int idx2 = tid + k*THREADS;       // 0..4607
        int r = idx2 / 9, c = idx2 - r*9; // row in [0,512), col float2 in [0,9)
        off2[k] = r*(NF/2) + fh*(NFH/2) + c;
    }

    for (int j = tid; j < CFH; j += THREADS) { bmax[j] = -1e30f; bmin[j] = 1e30f; }

    float S[2*NFH];
    #pragma unroll
    for (int j = 0; j < 2*NFH; j++) S[j] = 0.f;

    float2* u_sm2 = (float2*)u_sm;
    for (int Bi = ch*BCH; Bi < ch*BCH + BCH; Bi++) {
        const float2* up = (const float2*)(u + (size_t)(bi*BB + Bi)*SLICE);
        __syncthreads();
        #pragma unroll
        for (int k = 0; k < NLD; k++) u_sm2[tid + k*THREADS] = up[off2[k]];
        if (tid < NFH) a_row[tid] = g_asm[(bi*BB + Bi)*NF + fh*NFH + tid];
        __syncthreads();

        // norm over p per (C,fl); owner-thread-private running min/max over B
        for (int idx = tid; idx < CFH; idx += THREADS) {
            int Ci = idx / NFH, fl = idx - Ci*NFH;
            float acc = 0.f;
            #pragma unroll
            for (int p = 0; p < NP; p++) {
                float x = u_sm[(Ci*NP + p)*NFH + fl];
                acc = fmaf(x, x, acc);
            }
            float nr = sqrtf(acc);
            bmax[idx] = fmaxf(bmax[idx], nr);
            bmin[idx] = fminf(bmin[idx], nr);
        }
        // S0 += c0[fl]*u  (row-per-thread, trivial index math)
        #pragma unroll
        for (int rl = 0; rl < 2; rl++) {
            const float* us = u_sm + (tid + rl*THREADS)*NFH;
            #pragma unroll
            for (int fl = 0; fl < NFH; fl++)
                S[rl*NFH + fl] = fmaf(a_row[fl], us[fl], S[rl*NFH + fl]);
        }
    }
    // stage S rows into smem, write out coalesced with the same f-split mapping
    __syncthreads();
    #pragma unroll
    for (int rl = 0; rl < 2; rl++) {
        float* us = u_sm + (tid + rl*THREADS)*NFH;
        #pragma unroll
        for (int fl = 0; fl < NFH; fl++) us[fl] = S[rl*NFH + fl];
    }
    __syncthreads();
    float2* sp2 = (float2*)(g_Spart + (size_t)(bi*NCHUNK + ch)*SLICE);
    #pragma unroll
    for (int k = 0; k < NLD; k++) sp2[off2[k]] = u_sm2[tid + k*THREADS];

    for (int idx = tid; idx < CFH; idx += THREADS) {
        int Ci = idx / NFH, fl = idx - Ci*NFH;
        int go = bi*CF + Ci*NF + fh*NFH + fl;
        atomicMax(&g_mx[go], __float_as_int(bmax[idx]));
        atomicMin(&g_mn[go], __float_as_int(bmin[idx]));
    }
}

// ---------------- routing pass i>0 ----------------
__global__ __launch_bounds__(THREADS, 2)
void pass_kernel(const float* __restrict__ u) {
    extern __shared__ float sh[];
    float* u_sm  = sh;                  // SLICE_H
    float* w_sm  = sh + SLICE_H;        // SLICE_H
    float* s_sm  = w_sm + SLICE_H;      // CFH
    float* r_sm  = s_sm + CFH;          // CFH
    float* c_sm  = r_sm + CFH;          // CFH
    float* a_row = c_sm + CFH;          // 32

    int bid = blockIdx.x;
    int fh = bid & 1;
    int ch = (bid >> 1) % NCHUNK;
    int bi = bid / (NCHUNK*FSPLIT);
    int tid = threadIdx.x;

    int off2[NLD];
    #pragma unroll
    for (int k = 0; k < NLD; k++) {
        int idx2 = tid + k*THREADS;
        int r = idx2 / 9, c = idx2 - r*9;
        off2[k] = r*(NF/2) + fh*(NFH/2) + c;
    }

    // stage w (f-half) and s
    {
        float2* w_sm2 = (float2*)w_sm;
        const float2* wp = (const float2*)(g_w + (size_t)bi*SLICE);
        #pragma unroll
        for (int k = 0; k < NLD; k++) w_sm2[tid + k*THREADS] = wp[off2[k]];
        for (int j = tid; j < CFH; j += THREADS) {
            int Ci = j / NFH, fl = j - Ci*NFH;
            s_sm[j] = g_s[bi*CF + Ci*NF + fh*NFH + fl];
        }
    }

    float S[2*NFH];
    #pragma unroll
    for (int j = 0; j < 2*NFH; j++) S[j] = 0.f;

    float2* u_sm2 = (float2*)u_sm;
    for (int Bi = ch*BCH; Bi < ch*BCH + BCH; Bi++) {
        const float2* up = (const float2*)(u + (size_t)(bi*BB + Bi)*SLICE);
        __syncthreads();
        #pragma unroll
        for (int k = 0; k < NLD; k++) u_sm2[tid + k*THREADS] = up[off2[k]];
        if (tid < NFH) a_row[tid] = g_asm[(bi*BB + Bi)*NF + fh*NFH + tid];
        __syncthreads();

        // r[C,fl] = s * sum_p u*w
        for (int idx = tid; idx < CFH; idx += THREADS) {
            int Ci = idx / NFH, fl = idx - Ci*NFH;
            float acc = 0.f;
            #pragma unroll
            for (int p = 0; p < NP; p++) {
                int o = (Ci*NP + p)*NFH + fl;
                acc = fmaf(u_sm[o], w_sm[o], acc);
            }
            r_sm[idx] = acc * s_sm[idx];
        }
        __syncthreads();
        // softmax over C per fl; c = softmax * a * NC
        if (tid < NFH) {
            float m = -1e30f;
            #pragma unroll
            for (int Ci = 0; Ci < NC; Ci++) m = fmaxf(m, r_sm[Ci*NFH + tid]);
            float sum = 0.f;
            #pragma unroll
            for (int Ci = 0; Ci < NC; Ci++) {
                float e = __expf(r_sm[Ci*NFH + tid] - m);
                c_sm[Ci*NFH + tid] = e;
                sum += e;
            }
            float sc = a_row[tid] * (float)NC / sum;
            #pragma unroll
            for (int Ci = 0; Ci < NC; Ci++) c_sm[Ci*NFH + tid] *= sc;
        }
        __syncthreads();
        #pragma unroll
        for (int rl = 0; rl < 2; rl++) {
            int r = tid + rl*THREADS;
            const float* cs = c_sm + (r >> 4)*NFH;  // Ci = r/NP
            const float* us = u_sm + r*NFH;
            #pragma unroll
            for (int fl = 0; fl < NFH; fl++)
                S[rl*NFH + fl] = fmaf(cs[fl], us[fl], S[rl*NFH + fl]);
        }
    }
    __syncthreads();
    #pragma unroll
    for (int rl = 0; rl < 2; rl++) {
        float* us = u_sm + (tid + rl*THREADS)*NFH;
        #pragma unroll
        for (int fl = 0; fl < NFH; fl++) us[fl] = S[rl*NFH + fl];
    }
    __syncthreads();
    float2* sp2 = (float2*)(g_Spart + (size_t)(bi*NCHUNK + ch)*SLICE);
    #pragma unroll
    for (int k = 0; k < NLD; k++) sp2[off2[k]] = u_sm2[tid + k*THREADS];
}

// ---------------- coalesced chunk reduction: g_S = sum_ch g_Spart ----------------
__global__ void reduce_kernel() {
    int g = blockIdx.x * blockDim.x + threadIdx.x;   // < NB*SLICE/4
    int bi = g / (SLICE/4);
    int s4 = g - bi*(SLICE/4);
    float4 acc = make_float4(0.f, 0.f, 0.f, 0.f);
    const float4* sp = (const float4*)g_Spart;
    #pragma unroll
    for (int ch = 0; ch < NCHUNK; ch++) {
        float4 v = sp[(size_t)(bi*NCHUNK + ch)*(SLICE/4) + s4];
        acc.x += v.x; acc.y += v.y; acc.z += v.z; acc.w += v.w;
    }
    ((float4*)g_S)[g] = acc;
}

// ---------------- squash: 16-lane group per (b,C,f), lane = p ----------------
template<int IT>
__global__ void v_kernel(float* __restrict__ out) {
    int t = blockIdx.x * blockDim.x + threadIdx.x;   // < NB*CF*16
    int g = t >> 4;            // (b,C,f) group
    int p = t & 15;
    int bi = g / CF;
    int idx = g - bi*CF;
    int Ci = idx / NF, f = idx - Ci*NF;

    float s;
    if (IT == 0) {
        s = 1.f / (__int_as_float(g_mx[g]) - __int_as_float(g_mn[g]));
        if (p == 0) g_s[g] = s;
    } else {
        s = g_s[g];
    }

    int o = bi*SLICE + (Ci*NP + p)*NF + f;
    float acc = g_S[o] * s;
    float sn = acc * acc;
    #pragma unroll
    for (int sh = 8; sh >= 1; sh >>= 1)
        sn += __shfl_xor_sync(0xffffffffu, sn, sh, 16);
    float fac = (sn / (1.f + sn)) * rsqrtf(sn + EPS);
    float vp = acc * fac;

    if (IT < 2) {
        g_w[o] = (IT == 0) ? vp : (g_w[o] + vp);
    } else {
        out[((bi*NC + Ci)*NP + p)*NF + f] = vp;
        if (p == 0) out[NB*SLICE + g] = sqrtf(sn) * fac;
    }
}

// ---------------- launch ----------------
extern "C" void kernel_launch(void* const* d_in, const int* in_sizes, int n_in,
                              void* d_out, int out_size) {
    const float* u = (const float*)d_in[0];
    const float* a = (const float*)d_in[1];
    if (n_in >= 2 && in_sizes[0] < in_sizes[1]) {
        u = (const float*)d_in[1];
        a = (const float*)d_in[0];
    }
    float* out = (float*)d_out;

    const int SMEM0 = (SLICE_H + 2*CFH + 32) * sizeof(float);    // ~41.6 KB
    const int SMEM1 = (2*SLICE_H + 3*CFH + 32) * sizeof(float);  // ~80.8 KB
    cudaFuncSetAttribute(pass0_kernel, cudaFuncAttributeMaxDynamicSharedMemorySize, SMEM0);
    cudaFuncSetAttribute(pass_kernel,  cudaFuncAttributeMaxDynamicSharedMemorySize, SMEM1);

    const int GP = NB * NCHUNK * FSPLIT;      // 288 pass blocks
    const int GR = NB * SLICE / 4 / THREADS;  // 288 reduce blocks
    const int GV = NB * CF * 16 / THREADS;    // 1152 squash blocks

    init_kernel<<<(NB*CF + 255)/256, 256>>>();
    asm_kernel<<<NB*NF, BB>>>(a);

    pass0_kernel<<<GP, THREADS, SMEM0>>>(u);
    reduce_kernel<<<GR, THREADS>>>();
    v_kernel<0><<<GV, THREADS>>>(out);

    pass_kernel<<<GP, THREADS, SMEM1>>>(u);
    reduce_kernel<<<GR, THREADS>>>();
    v_kernel<1><<<GV, THREADS>>>(out);

    pass_kernel<<<GP, THREADS, SMEM1>>>(u);
    reduce_kernel<<<GR, THREADS>>>();
    v_kernel<2><<<GV, THREADS>>>(out);
}

// round 6
// speedup vs baseline: 1.4822x; 1.4822x over previous
#include <cuda_runtime.h>
#include <cstdint>

// Problem constants
#define NB 16        // batch
#define BB 288       // input capsules
#define NC 32        // output capsules (softmax dim)
#define NP 16        // pose dim
#define NF 36        // f*f positions
#define SLICE (NC*NP*NF)   // 18432 floats = one (b,B) slice
#define CF (NC*NF)         // 1152
#define NCH 9              // B chunks
#define BCH 32             // B per chunk
#define T0 512
#define EPS 1e-5f

// ---------------- device scratch (small: ~12.7 MB total) ----------------
__device__ float g_asm[NB*BB*NF];                 // softmax_B(a)
__device__ float g_Spart[(size_t)NB*NCH*SLICE];   // partial S, (C,f,p) layout per (b,ch)
__device__ float g_w[NB*SLICE];                   // s-premultiplied running sum of v, (C,p,f)
__device__ float g_s[NB*CF];                      // 1/(mx-mn)
__device__ int   g_mx[NB*CF];
__device__ int   g_mn[NB*CF];

// ---------------- cp.async helpers ----------------
__device__ __forceinline__ void cp_async16(float* smem_ptr, const float4* gptr) {
    uint32_t sa = (uint32_t)__cvta_generic_to_shared(smem_ptr);
    asm volatile("cp.async.cg.shared.global [%0], [%1], 16;" :: "r"(sa), "l"(gptr));
}
__device__ __forceinline__ void cp_commit() { asm volatile("cp.async.commit_group;"); }
__device__ __forceinline__ void cp_wait1()  { asm volatile("cp.async.wait_group 1;" ::: "memory"); }
__device__ __forceinline__ void cp_wait0()  { asm volatile("cp.async.wait_group 0;" ::: "memory"); }

// ---------------- init ----------------
__global__ void init_kernel() {
    int g = blockIdx.x * blockDim.x + threadIdx.x;
    if (g < NB*CF) { g_mx[g] = 0; g_mn[g] = 0x7F800000; }
}

// ---------------- softmax of a over B, per (b,f) ----------------
__global__ void asm_kernel(const float* __restrict__ a) {
    __shared__ float red[BB];
    int bf = blockIdx.x;
    int bi = bf / NF, f = bf - bi*NF;
    int t = threadIdx.x;
    float x = a[(bi*BB + t)*NF + f];
    red[t] = x; __syncthreads();
    for (int st = 256; st >= 1; st >>= 1) {
        if (t < st && t + st < BB) red[t] = fmaxf(red[t], red[t + st]);
        __syncthreads();
    }
    float m = red[0]; __syncthreads();
    float e = __expf(x - m);
    red[t] = e; __syncthreads();
    for (int st = 256; st >= 1; st >>= 1) {
        if (t < st && t + st < BB) red[t] += red[t + st];
        __syncthreads();
    }
    g_asm[(bi*BB + t)*NF + f] = e / red[0];
}

// ---------------- pass 0: norms->min/max + S0 = sum_B c0*u (cp.async pipelined) ----------------
__global__ __launch_bounds__(T0, 1)
void pass0_kernel(const float* __restrict__ u) {
    extern __shared__ float sh[];
    float* ubuf  = sh;              // 2*SLICE (double buffer)
    float* bmax  = sh + 2*SLICE;    // CF
    float* bmin  = bmax + CF;       // CF
    float* a_row = bmin + CF;       // 40
    int bi = blockIdx.x / NCH, ch = blockIdx.x % NCH;
    int tid = threadIdx.x;

    // owner-thread-private min/max slots (same idx set written & read by same thread)
    #pragma unroll
    for (int q = 0; q < 3; q++) {
        int idx = tid + q*T0;
        if (idx < CF) { bmax[idx] = -1e30f; bmin[idx] = 1e30f; }
    }

    int B0 = ch*BCH;
    {   // prefetch iter 0
        const float4* up = (const float4*)(u + (size_t)(bi*BB + B0)*SLICE);
        #pragma unroll
        for (int k = 0; k < 9; k++) cp_async16(ubuf + 4*(tid + k*T0), up + tid + k*T0);
        cp_commit();
    }

    float S[NF];
    #pragma unroll
    for (int j = 0; j < NF; j++) S[j] = 0.f;

    for (int i = 0; i < BCH; i++) {
        __syncthreads();   // prev compute done; buffer (i+1)&1 free
        if (tid < NF) a_row[tid] = g_asm[(bi*BB + B0 + i)*NF + tid];
        if (i + 1 < BCH) {
            const float4* up = (const float4*)(u + (size_t)(bi*BB + B0 + i + 1)*SLICE);
            float* dst = ubuf + ((i+1)&1)*SLICE;
            #pragma unroll
            for (int k = 0; k < 9; k++) cp_async16(dst + 4*(tid + k*T0), up + tid + k*T0);
            cp_commit();
            cp_wait1();
        } else cp_wait0();
        __syncthreads();   // buffer i&1 + a_row visible

        const float* usm = ubuf + (i&1)*SLICE;
        // norms over p per (C,f)
        #pragma unroll
        for (int q = 0; q < 3; q++) {
            int idx = tid + q*T0;
            if (idx < CF) {
                int Ci = idx / NF, f = idx - Ci*NF;
                float acc = 0.f;
                #pragma unroll
                for (int p = 0; p < NP; p++) {
                    float x = usm[(Ci*NP + p)*NF + f];
                    acc = fmaf(x, x, acc);
                }
                float nr = sqrtf(acc);
                bmax[idx] = fmaxf(bmax[idx], nr);
                bmin[idx] = fminf(bmin[idx], nr);
            }
        }
        // S0 += c0[f]*u  (row-per-thread, conflict-free LDS.128)
        const float4* ur4 = (const float4*)(usm + tid*NF);
        #pragma unroll
        for (int q = 0; q < 9; q++) {
            float4 uq = ur4[q];
            S[4*q+0] = fmaf(a_row[4*q+0], uq.x, S[4*q+0]);
            S[4*q+1] = fmaf(a_row[4*q+1], uq.y, S[4*q+1]);
            S[4*q+2] = fmaf(a_row[4*q+2], uq.z, S[4*q+2]);
            S[4*q+3] = fmaf(a_row[4*q+3], uq.w, S[4*q+3]);
        }
    }
    __syncthreads();
    // global min/max
    #pragma unroll
    for (int q = 0; q < 3; q++) {
        int idx = tid + q*T0;
        if (idx < CF) {
            atomicMax(&g_mx[bi*CF + idx], __float_as_int(bmax[idx]));
            atomicMin(&g_mn[bi*CF + idx], __float_as_int(bmin[idx]));
        }
    }
    // stage S in (C,f,p) order, write Spart coalesced
    {
        int Ci = tid >> 4, p = tid & 15;
        #pragma unroll
        for (int f = 0; f < NF; f++) ubuf[(Ci*NF + f)*NP + p] = S[f];
    }
    __syncthreads();
    float4* sp4 = (float4*)(g_Spart + (size_t)(bi*NCH + ch)*SLICE);
    #pragma unroll
    for (int k = 0; k < 9; k++) sp4[tid + k*T0] = ((float4*)ubuf)[tid + k*T0];
}

// ---------------- routing pass i>0 (cp.async pipelined) ----------------
__global__ __launch_bounds__(T0, 1)
void pass_kernel(const float* __restrict__ u) {
    extern __shared__ float sh[];
    float* ubuf  = sh;              // 2*SLICE
    float* w_sm  = sh + 2*SLICE;    // SLICE  (s-premultiplied w)
    float* r_sm  = w_sm + SLICE;    // CF (r, then c in-place)
    float* a_row = r_sm + CF;       // 40
    int bi = blockIdx.x / NCH, ch = blockIdx.x % NCH;
    int tid = threadIdx.x;
    int Ci_r = tid >> 4;            // row-mapped C index

    // stage w once (coalesced)
    {   const float4* wp = (const float4*)(g_w + (size_t)bi*SLICE);
        #pragma unroll
        for (int k = 0; k < 9; k++) ((float4*)w_sm)[tid + k*T0] = wp[tid + k*T0];
    }
    int B0 = ch*BCH;
    {   const float4* up = (const float4*)(u + (size_t)(bi*BB + B0)*SLICE);
        #pragma unroll
        for (int k = 0; k < 9; k++) cp_async16(ubuf + 4*(tid + k*T0), up + tid + k*T0);
        cp_commit();
    }

    float S[NF];
    #pragma unroll
    for (int j = 0; j < NF; j++) S[j] = 0.f;

    for (int i = 0; i < BCH; i++) {
        __syncthreads();
        if (tid < NF) a_row[tid] = g_asm[(bi*BB + B0 + i)*NF + tid];
        if (i + 1 < BCH) {
            const float4* up = (const float4*)(u + (size_t)(bi*BB + B0 + i + 1)*SLICE);
            float* dst = ubuf + ((i+1)&1)*SLICE;
            #pragma unroll
            for (int k = 0; k < 9; k++) cp_async16(dst + 4*(tid + k*T0), up + tid + k*T0);
            cp_commit();
            cp_wait1();
        } else cp_wait0();
        __syncthreads();

        const float* usm = ubuf + (i&1)*SLICE;
        // r[C,f] = u · w_pre  (w premultiplied by s)
        #pragma unroll
        for (int q = 0; q < 3; q++) {
            int idx = tid + q*T0;
            if (idx < CF) {
                int Ci = idx / NF, f = idx - Ci*NF;
                float acc = 0.f;
                #pragma unroll
                for (int p = 0; p < NP; p++) {
                    int o = (Ci*NP + p)*NF + f;
                    acc = fmaf(usm[o], w_sm[o], acc);
                }
                r_sm[idx] = acc;
            }
        }
        __syncthreads();
        // softmax over C per f, parallel over 144 threads (4 lanes per f, 8 C each)
        if (tid < 144) {
            unsigned mask = (tid < 128) ? 0xffffffffu : 0x0000ffffu;
            int f = tid >> 2, sub = tid & 3;
            float* col = r_sm + f;
            int base = sub * 8;
            float m = -1e30f;
            #pragma unroll
            for (int c = 0; c < 8; c++) m = fmaxf(m, col[(base + c)*NF]);
            m = fmaxf(m, __shfl_xor_sync(mask, m, 1, 4));
            m = fmaxf(m, __shfl_xor_sync(mask, m, 2, 4));
            float e[8]; float sum = 0.f;
            #pragma unroll
            for (int c = 0; c < 8; c++) { e[c] = __expf(col[(base + c)*NF] - m); sum += e[c]; }
            sum += __shfl_xor_sync(mask, sum, 1, 4);
            sum += __shfl_xor_sync(mask, sum, 2, 4);
            float sc = a_row[f] * (float)NC / sum;
            #pragma unroll
            for (int c = 0; c < 8; c++) col[(base + c)*NF] = e[c] * sc;
        }
        __syncthreads();
        // S += c[C,f] * u  (row-per-thread, conflict-free LDS.128; c base constant per thread)
        const float4* ur4 = (const float4*)(usm + tid*NF);
        const float* cb = r_sm + Ci_r*NF;
        #pragma unroll
        for (int q = 0; q < 9; q++) {
            float4 uq = ur4[q];
            S[4*q+0] = fmaf(cb[4*q+0], uq.x, S[4*q+0]);
            S[4*q+1] = fmaf(cb[4*q+1], uq.y, S[4*q+1]);
            S[4*q+2] = fmaf(cb[4*q+2], uq.z, S[4*q+2]);
            S[4*q+3] = fmaf(cb[4*q+3], uq.w, S[4*q+3]);
        }
    }
    __syncthreads();
    // stage S in (C,f,p), write Spart coalesced
    {
        int p = tid & 15;
        #pragma unroll
        for (int f = 0; f < NF; f++) ubuf[(Ci_r*NF + f)*NP + p] = S[f];
    }
    __syncthreads();
    float4* sp4 = (float4*)(g_Spart + (size_t)(bi*NCH + ch)*SLICE);
    #pragma unroll
    for (int k = 0; k < 9; k++) sp4[tid + k*T0] = ((float4*)ubuf)[tid + k*T0];
}

// ---------------- fused chunk-reduce + squash (16-lane group per (b,C,f), lane = p) ----------------
template<int IT>
__global__ void v_kernel(float* __restrict__ out) {
    int t = blockIdx.x * blockDim.x + threadIdx.x;   // exactly NB*CF*16 threads
    int g = t >> 4, p = t & 15;
    int bi = g / CF, idx = g - bi*CF;                // idx = Ci*NF + f

    // coalesced reduce over chunks ((C,f,p) layout: consecutive t -> consecutive addr)
    const float* sp = g_Spart + (size_t)bi*NCH*SLICE + idx*NP + p;
    float acc = 0.f;
    #pragma unroll
    for (int ch = 0; ch < NCH; ch++) acc += sp[(size_t)ch*SLICE];

    float s;
    if (IT == 0) {
        s = 1.f / (__int_as_float(g_mx[g]) - __int_as_float(g_mn[g]));
        if (p == 0) g_s[g] = s;
    } else {
        s = g_s[g];
    }

    acc *= s;
    float sn = acc * acc;
    #pragma unroll
    for (int sh = 8; sh >= 1; sh >>= 1)
        sn += __shfl_xor_sync(0xffffffffu, sn, sh, 16);
    float fac = (sn / (1.f + sn)) * rsqrtf(sn + EPS);
    float vp = acc * fac;

    int Ci = idx / NF, f = idx - Ci*NF;
    if (IT < 2) {
        int o = bi*SLICE + (Ci*NP + p)*NF + f;       // (C,p,f) layout, s-premultiplied
        g_w[o] = (IT == 0) ? (s * vp) : (g_w[o] + s * vp);
    } else {
        out[((bi*NC + Ci)*NP + p)*NF + f] = vp;
        if (p == 0) out[NB*SLICE + g] = sqrtf(sn) * fac;
    }
}

// ---------------- launch ----------------
extern "C" void kernel_launch(void* const* d_in, const int* in_sizes, int n_in,
                              void* d_out, int out_size) {
    const float* u = (const float*)d_in[0];
    const float* a = (const float*)d_in[1];
    if (n_in >= 2 && in_sizes[0] < in_sizes[1]) {
        u = (const float*)d_in[1];
        a = (const float*)d_in[0];
    }
    float* out = (float*)d_out;

    const int SMEM0 = (2*SLICE + 2*CF + 40) * sizeof(float);   // 156,832 B
    const int SMEM1 = (3*SLICE + CF + 40) * sizeof(float);     // 225,952 B
    cudaFuncSetAttribute(pass0_kernel, cudaFuncAttributeMaxDynamicSharedMemorySize, SMEM0);
    cudaFuncSetAttribute(pass_kernel,  cudaFuncAttributeMaxDynamicSharedMemorySize, SMEM1);

    const int GP = NB * NCH;                // 144 pass blocks (1/SM)
    const int GV = NB * CF * 16 / 256;      // 1152 v blocks

    init_kernel<<<(NB*CF + 255)/256, 256>>>();
    asm_kernel<<<NB*NF, BB>>>(a);

    pass0_kernel<<<GP, T0, SMEM0>>>(u);
    v_kernel<0><<<GV, 256>>>(out);

    pass_kernel<<<GP, T0, SMEM1>>>(u);
    v_kernel<1><<<GV, 256>>>(out);

    pass_kernel<<<GP, T0, SMEM1>>>(u);
    v_kernel<2><<<GV, 256>>>(out);
}

// round 8
// speedup vs baseline: 1.7145x; 1.1568x over previous
#include <cuda_runtime.h>
#include <cstdint>

// Problem constants
#define NB 16        // batch
#define BB 288       // input capsules
#define NC 32        // output capsules (softmax dim)
#define NP 16        // pose dim
#define NF 36        // f*f positions
#define SLICE (NC*NP*NF)   // 18432 floats = one (b,B) slice
#define CF (NC*NF)         // 1152
#define NCH 9              // B chunks
#define BCH 32             // B per chunk
#define TPASS 384          // pass threads: 1152/384 = 3 (C,f) pairs each
#define EPS 1e-5f

// ---------------- device scratch (~12.7 MB) ----------------
__device__ float g_asm[NB*BB*NF];                 // softmax_B(a)
__device__ float g_Spart[(size_t)NB*NCH*SLICE];   // partial S, (C,f,p) layout per (b,ch)
__device__ float g_w[NB*SLICE];                   // s-premultiplied running sum of v, (C,f,p)
__device__ float g_s[NB*CF];                      // 1/(mx-mn)
__device__ int   g_mx[NB*CF];
__device__ int   g_mn[NB*CF];

// ---------------- cp.async helpers ----------------
__device__ __forceinline__ void cp_async16(float* smem_ptr, const float4* gptr) {
    uint32_t sa = (uint32_t)__cvta_generic_to_shared(smem_ptr);
    asm volatile("cp.async.cg.shared.global [%0], [%1], 16;" :: "r"(sa), "l"(gptr));
}
__device__ __forceinline__ void cp_commit() { asm volatile("cp.async.commit_group;"); }
__device__ __forceinline__ void cp_wait1()  { asm volatile("cp.async.wait_group 1;" ::: "memory"); }
__device__ __forceinline__ void cp_wait0()  { asm volatile("cp.async.wait_group 0;" ::: "memory"); }

// ---------------- init ----------------
__global__ void init_kernel() {
    int g = blockIdx.x * blockDim.x + threadIdx.x;
    if (g < NB*CF) { g_mx[g] = 0; g_mn[g] = 0x7F800000; }
}

// ---------------- softmax of a over B, per (b,f) ----------------
__global__ void asm_kernel(const float* __restrict__ a) {
    __shared__ float red[BB];
    int bf = blockIdx.x;
    int bi = bf / NF, f = bf - bi*NF;
    int t = threadIdx.x;
    float x = a[(bi*BB + t)*NF + f];
    red[t] = x; __syncthreads();
    for (int st = 256; st >= 1; st >>= 1) {
        if (t < st && t + st < BB) red[t] = fmaxf(red[t], red[t + st]);
        __syncthreads();
    }
    float m = red[0]; __syncthreads();
    float e = __expf(x - m);
    red[t] = e; __syncthreads();
    for (int st = 256; st >= 1; st >>= 1) {
        if (t < st && t + st < BB) red[t] += red[t + st];
        __syncthreads();
    }
    g_asm[(bi*BB + t)*NF + f] = e / red[0];
}

// ---------------- pass 0: u read ONCE/iter; norms + S0 from registers ----------------
__global__ __launch_bounds__(TPASS, 1)
void pass0_kernel(const float* __restrict__ u) {
    extern __shared__ float sh[];
    float* ubuf  = sh;              // 2*SLICE double buffer
    float* a_row = sh + 2*SLICE;    // 40
    int bi = blockIdx.x / NCH, ch = blockIdx.x % NCH;
    int tid = threadIdx.x;

    int off[3], fi[3];
    #pragma unroll
    for (int q = 0; q < 3; q++) {
        int idx = tid + q*TPASS;          // < 1152
        int Ci = idx / NF; fi[q] = idx - Ci*NF;
        off[q] = Ci*(NP*NF) + fi[q];      // + p*NF strides
    }

    float S[48];
    #pragma unroll
    for (int j = 0; j < 48; j++) S[j] = 0.f;
    float mx[3] = {-1e30f, -1e30f, -1e30f};
    float mn[3] = { 1e30f,  1e30f,  1e30f};

    int B0 = ch*BCH;
    {   const float4* up = (const float4*)(u + (size_t)(bi*BB + B0)*SLICE);
        #pragma unroll
        for (int k = 0; k < 12; k++) cp_async16(ubuf + 4*(tid + k*TPASS), up + tid + k*TPASS);
        cp_commit();
    }

    for (int i = 0; i < BCH; i++) {
        __syncthreads();                              // prev compute done; next buffer free
        if (tid < NF) a_row[tid] = g_asm[(bi*BB + B0 + i)*NF + tid];
        if (i + 1 < BCH) {
            const float4* up = (const float4*)(u + (size_t)(bi*BB + B0 + i + 1)*SLICE);
            float* dst = ubuf + ((i+1)&1)*SLICE;
            #pragma unroll
            for (int k = 0; k < 12; k++) cp_async16(dst + 4*(tid + k*TPASS), up + tid + k*TPASS);
            cp_commit();
            cp_wait1();
        } else cp_wait0();
        __syncthreads();                              // buffer i + a_row visible

        const float* usm = ubuf + (i&1)*SLICE;
        #pragma unroll
        for (int q = 0; q < 3; q++) {
            float aw = a_row[fi[q]];
            float nrm = 0.f;
            #pragma unroll
            for (int p = 0; p < NP; p++) {
                float x = usm[off[q] + p*NF];
                nrm = fmaf(x, x, nrm);
                S[q*16 + p] = fmaf(aw, x, S[q*16 + p]);
            }
            float nr = sqrtf(nrm);
            mx[q] = fmaxf(mx[q], nr);
            mn[q] = fminf(mn[q], nr);
        }
    }
    // min/max atomics + coalesced (C,f,p) partial-S writeback
    float4* sp4 = (float4*)(g_Spart + (size_t)(bi*NCH + ch)*SLICE);
    #pragma unroll
    for (int q = 0; q < 3; q++) {
        int idx = tid + q*TPASS;
        atomicMax(&g_mx[bi*CF + idx], __float_as_int(mx[q]));
        atomicMin(&g_mn[bi*CF + idx], __float_as_int(mn[q]));
        #pragma unroll
        for (int j = 0; j < 4; j++)
            sp4[idx*4 + j] = make_float4(S[q*16+4*j], S[q*16+4*j+1], S[q*16+4*j+2], S[q*16+4*j+3]);
    }
}

// ---------------- routing pass i>0: w + S in registers ----------------
__global__ __launch_bounds__(TPASS, 1)
void pass_kernel(const float* __restrict__ u) {
    extern __shared__ float sh[];
    float* ubuf  = sh;              // 2*SLICE
    float* c_sm  = sh + 2*SLICE;    // CF (raw dot, then c in-place)
    float* a_row = c_sm + CF;       // 40
    int bi = blockIdx.x / NCH, ch = blockIdx.x % NCH;
    int tid = threadIdx.x;

    int off[3], fi[3], idxq[3];
    #pragma unroll
    for (int q = 0; q < 3; q++) {
        int idx = tid + q*TPASS;
        int Ci = idx / NF; fi[q] = idx - Ci*NF;
        off[q] = Ci*(NP*NF) + fi[q];
        idxq[q] = idx;
    }

    // w registers: (C,f,p) layout -> 4 LDG.128 per pair
    float w[48];
    #pragma unroll
    for (int q = 0; q < 3; q++) {
        const float4* wp = (const float4*)(g_w + (size_t)bi*SLICE + idxq[q]*NP);
        #pragma unroll
        for (int j = 0; j < 4; j++) {
            float4 v4 = wp[j];
            w[q*16+4*j] = v4.x; w[q*16+4*j+1] = v4.y; w[q*16+4*j+2] = v4.z; w[q*16+4*j+3] = v4.w;
        }
    }

    float S[48];
    #pragma unroll
    for (int j = 0; j < 48; j++) S[j] = 0.f;

    int B0 = ch*BCH;
    {   const float4* up = (const float4*)(u + (size_t)(bi*BB + B0)*SLICE);
        #pragma unroll
        for (int k = 0; k < 12; k++) cp_async16(ubuf + 4*(tid + k*TPASS), up + tid + k*TPASS);
        cp_commit();
    }

    for (int i = 0; i < BCH; i++) {
        __syncthreads();
        if (tid < NF) a_row[tid] = g_asm[(bi*BB + B0 + i)*NF + tid];
        if (i + 1 < BCH) {
            const float4* up = (const float4*)(u + (size_t)(bi*BB + B0 + i + 1)*SLICE);
            float* dst = ubuf + ((i+1)&1)*SLICE;
            #pragma unroll
            for (int k = 0; k < 12; k++) cp_async16(dst + 4*(tid + k*TPASS), up + tid + k*TPASS);
            cp_commit();
            cp_wait1();
        } else cp_wait0();
        __syncthreads();

        const float* usm = ubuf + (i&1)*SLICE;
        // raw dot r[C,f] = sum_p u * w_pre   (w premultiplied by s)
        #pragma unroll
        for (int q = 0; q < 3; q++) {
            float acc = 0.f;
            #pragma unroll
            for (int p = 0; p < NP; p++)
                acc = fmaf(usm[off[q] + p*NF], w[q*16 + p], acc);
            c_sm[idxq[q]] = acc;
        }
        __syncthreads();
        // softmax over C per f (144 threads: 4 lanes/f, 8 C each)
        if (tid < 144) {
            unsigned mask = (tid < 128) ? 0xffffffffu : 0x0000ffffu;
            int f = tid >> 2, sub = tid & 3;
            float* col = c_sm + f;
            int base = sub * 8;
            float m = -1e30f;
            #pragma unroll
            for (int c = 0; c < 8; c++) m = fmaxf(m, col[(base + c)*NF]);
            m = fmaxf(m, __shfl_xor_sync(mask, m, 1, 4));
            m = fmaxf(m, __shfl_xor_sync(mask, m, 2, 4));
            float e[8]; float sum = 0.f;
            #pragma unroll
            for (int c = 0; c < 8; c++) { e[c] = __expf(col[(base + c)*NF] - m); sum += e[c]; }
            sum += __shfl_xor_sync(mask, sum, 1, 4);
            sum += __shfl_xor_sync(mask, sum, 2, 4);
            float sc = a_row[f] * (float)NC / sum;
            #pragma unroll
            for (int c = 0; c < 8; c++) col[(base + c)*NF] = e[c] * sc;
        }
        __syncthreads();
        // S += c * u
        #pragma unroll
        for (int q = 0; q < 3; q++) {
            float cv = c_sm[idxq[q]];
            #pragma unroll
            for (int p = 0; p < NP; p++)
                S[q*16 + p] = fmaf(cv, usm[off[q] + p*NF], S[q*16 + p]);
        }
    }
    float4* sp4 = (float4*)(g_Spart + (size_t)(bi*NCH + ch)*SLICE);
    #pragma unroll
    for (int q = 0; q < 3; q++) {
        #pragma unroll
        for (int j = 0; j < 4; j++)
            sp4[idxq[q]*4 + j] = make_float4(S[q*16+4*j], S[q*16+4*j+1], S[q*16+4*j+2], S[q*16+4*j+3]);
    }
}

// ---------------- fused chunk-reduce + squash: float4 over p, 4-lane groups ----------------
template<int IT>
__global__ void v_kernel(float* __restrict__ out) {
    int t = blockIdx.x * blockDim.x + threadIdx.x;   // exactly NB*CF*4 threads
    int g = t >> 2, pq = t & 3;
    int bi = g / CF, idx = g - bi*CF;                // idx = Ci*NF + f

    const float4* sp = (const float4*)g_Spart + (size_t)bi*NCH*(SLICE/4) + idx*4 + pq;
    float4 acc = make_float4(0.f, 0.f, 0.f, 0.f);
    #pragma unroll
    for (int ch = 0; ch < NCH; ch++) {
        float4 v = sp[(size_t)ch*(SLICE/4)];
        acc.x += v.x; acc.y += v.y; acc.z += v.z; acc.w += v.w;
    }

    float s;
    if (IT == 0) {
        s = 1.f / (__int_as_float(g_mx[g]) - __int_as_float(g_mn[g]));
        if (pq == 0) g_s[g] = s;
    } else {
        s = g_s[g];
    }

    acc.x *= s; acc.y *= s; acc.z *= s; acc.w *= s;
    float sn = acc.x*acc.x + acc.y*acc.y + acc.z*acc.z + acc.w*acc.w;
    sn += __shfl_xor_sync(0xffffffffu, sn, 1, 4);
    sn += __shfl_xor_sync(0xffffffffu, sn, 2, 4);
    float fac = (sn / (1.f + sn)) * rsqrtf(sn + EPS);

    if (IT < 2) {
        float4* wp = (float4*)(g_w + (size_t)bi*SLICE + idx*NP) + pq;
        float sf = s * fac;
        float4 nv = make_float4(acc.x*sf, acc.y*sf, acc.z*sf, acc.w*sf);
        if (IT == 1) {
            float4 ow = wp[0];
            nv.x += ow.x; nv.y += ow.y; nv.z += ow.z; nv.w += ow.w;
        }
        wp[0] = nv;
    } else {
        int Ci = idx / NF, f = idx - Ci*NF;
        float* ob = out + ((size_t)(bi*NC + Ci)*NP + pq*4)*NF + f;
        ob[0]      = acc.x * fac;
        ob[NF]     = acc.y * fac;
        ob[2*NF]   = acc.z * fac;
        ob[3*NF]   = acc.w * fac;
        if (pq == 0) out[NB*SLICE + g] = sqrtf(sn) * fac;
    }
}

// ---------------- launch ----------------
extern "C" void kernel_launch(void* const* d_in, const int* in_sizes, int n_in,
                              void* d_out, int out_size) {
    const float* u = (const float*)d_in[0];
    const float* a = (const float*)d_in[1];
    if (n_in >= 2 && in_sizes[0] < in_sizes[1]) {
        u = (const float*)d_in[1];
        a = (const float*)d_in[0];
    }
    float* out = (float*)d_out;

    const int SMEM0 = (2*SLICE + 40) * sizeof(float);        // ~147.6 KB
    const int SMEM1 = (2*SLICE + CF + 40) * sizeof(float);   // ~152.2 KB
    cudaFuncSetAttribute(pass0_kernel, cudaFuncAttributeMaxDynamicSharedMemorySize, SMEM0);
    cudaFuncSetAttribute(pass_kernel,  cudaFuncAttributeMaxDynamicSharedMemorySize, SMEM1);

    const int GP = NB * NCH;               // 144 pass blocks (1/SM)
    const int GV = NB * CF * 4 / 256;      // 288 v blocks

    init_kernel<<<(NB*CF + 255)/256, 256>>>();
    asm_kernel<<<NB*NF, BB>>>(a);

    pass0_kernel<<<GP, TPASS, SMEM0>>>(u);
    v_kernel<0><<<GV, 256>>>(out);

    pass_kernel<<<GP, TPASS, SMEM1>>>(u);
    v_kernel<1><<<GV, 256>>>(out);

    pass_kernel<<<GP, TPASS, SMEM1>>>(u);
    v_kernel<2><<<GV, 256>>>(out);
}

// round 10
// speedup vs baseline: 1.8549x; 1.0819x over previous
#include <cuda_runtime.h>
#include <cstdint>

// Problem constants
#define NB 16        // batch
#define BB 288       // input capsules
#define NC 32        // output capsules (softmax dim)
#define NP 16        // pose dim
#define NF 36        // f*f positions
#define SLICE (NC*NP*NF)   // 18432 floats = one (b,B) slice
#define CF (NC*NF)         // 1152
#define NCH 9              // B chunks
#define BCH 32             // B per chunk
#define TPASS 384          // pass threads: 1152/384 = 3 (C,f) pairs each
#define EPS 1e-5f

// ---------------- device scratch (~12.7 MB) ----------------
__device__ float g_asm[NB*BB*NF];                 // softmax_B(a)
__device__ float g_Spart[(size_t)NB*NCH*SLICE];   // partial S, (C,f,p) layout per (b,ch)
__device__ float g_w[NB*SLICE];                   // s-premultiplied running sum of v, (C,f,p)
__device__ float g_s[NB*CF];                      // 1/(mx-mn)
__device__ int   g_mx[NB*CF];
__device__ int   g_mn[NB*CF];

// ---------------- cp.async helpers ----------------
__device__ __forceinline__ void cp_async16(float* smem_ptr, const float4* gptr) {
    uint32_t sa = (uint32_t)__cvta_generic_to_shared(smem_ptr);
    asm volatile("cp.async.cg.shared.global [%0], [%1], 16;" :: "r"(sa), "l"(gptr));
}
__device__ __forceinline__ void cp_commit() { asm volatile("cp.async.commit_group;"); }
__device__ __forceinline__ void cp_wait2()  { asm volatile("cp.async.wait_group 2;" ::: "memory"); }

// ---------------- init ----------------
__global__ void init_kernel() {
    int g = blockIdx.x * blockDim.x + threadIdx.x;
    if (g < NB*CF) { g_mx[g] = 0; g_mn[g] = 0x7F800000; }
}

// ---------------- softmax of a over B, per (b,f) ----------------
__global__ void asm_kernel(const float* __restrict__ a) {
    __shared__ float red[BB];
    int bf = blockIdx.x;
    int bi = bf / NF, f = bf - bi*NF;
    int t = threadIdx.x;
    float x = a[(bi*BB + t)*NF + f];
    red[t] = x; __syncthreads();
    for (int st = 256; st >= 1; st >>= 1) {
        if (t < st && t + st < BB) red[t] = fmaxf(red[t], red[t + st]);
        __syncthreads();
    }
    float m = red[0]; __syncthreads();
    float e = __expf(x - m);
    red[t] = e; __syncthreads();
    for (int st = 256; st >= 1; st >>= 1) {
        if (t < st && t + st < BB) red[t] += red[t + st];
        __syncthreads();
    }
    g_asm[(bi*BB + t)*NF + f] = e / red[0];
}

// ---------------- pass 0: depth-3 pipeline; norms + S0 from registers ----------------
__global__ __launch_bounds__(TPASS, 1)
void pass0_kernel(const float* __restrict__ u) {
    extern __shared__ float sh[];
    float* ubuf  = sh;              // 3*SLICE triple buffer
    float* a_all = sh + 3*SLICE;    // BCH*NF = 1152 (all a-rows for this chunk)
    int bi = blockIdx.x / NCH, ch = blockIdx.x % NCH;
    int tid = threadIdx.x;
    int B0 = ch*BCH;

    int off[3], fi[3];
    #pragma unroll
    for (int q = 0; q < 3; q++) {
        int idx = tid + q*TPASS;          // < 1152
        int Ci = idx / NF; fi[q] = idx - Ci*NF;
        off[q] = Ci*(NP*NF) + fi[q];      // + p*NF strides
    }

    // preload all 32 a-rows (contiguous)
    #pragma unroll
    for (int q = 0; q < 3; q++)
        a_all[tid + q*TPASS] = g_asm[(bi*BB + B0)*NF + tid + q*TPASS];

    float S[48];
    #pragma unroll
    for (int j = 0; j < 48; j++) S[j] = 0.f;
    float mx[3] = {-1e30f, -1e30f, -1e30f};
    float mn[3] = { 1e30f,  1e30f,  1e30f};

    // prologue: prefetch iters 0 and 1
    #pragma unroll
    for (int pi = 0; pi < 2; pi++) {
        const float4* up = (const float4*)(u + (size_t)(bi*BB + B0 + pi)*SLICE);
        float* dst = ubuf + pi*SLICE;
        #pragma unroll
        for (int k = 0; k < 12; k++) cp_async16(dst + 4*(tid + k*TPASS), up + tid + k*TPASS);
        cp_commit();
    }

    int bufc = 0;   // buffer of iter i
    int bufn = 2;   // buffer receiving iter i+2
    for (int i = 0; i < BCH; i++) {
        __syncthreads();                              // compute i-1 done; bufn free
        if (i + 2 < BCH) {
            const float4* up = (const float4*)(u + (size_t)(bi*BB + B0 + i + 2)*SLICE);
            float* dst = ubuf + bufn*SLICE;
            #pragma unroll
            for (int k = 0; k < 12; k++) cp_async16(dst + 4*(tid + k*TPASS), up + tid + k*TPASS);
        }
        cp_commit();                                  // empty group ok at tail
        cp_wait2();                                   // group i complete
        __syncthreads();                              // buffer i visible

        const float* usm = ubuf + bufc*SLICE;
        const float* ar = a_all + i*NF;
        #pragma unroll
        for (int q = 0; q < 3; q++) {
            float aw = ar[fi[q]];
            float nrm = 0.f;
            #pragma unroll
            for (int p = 0; p < NP; p++) {
                float x = usm[off[q] + p*NF];
                nrm = fmaf(x, x, nrm);
                S[q*16 + p] = fmaf(aw, x, S[q*16 + p]);
            }
            float nr = sqrtf(nrm);
            mx[q] = fmaxf(mx[q], nr);
            mn[q] = fminf(mn[q], nr);
        }
        bufc = (bufc + 1 == 3) ? 0 : bufc + 1;
        bufn = (bufn + 1 == 3) ? 0 : bufn + 1;
    }
    // min/max atomics + coalesced (C,f,p) partial-S writeback
    float4* sp4 = (float4*)(g_Spart + (size_t)(bi*NCH + ch)*SLICE);
    #pragma unroll
    for (int q = 0; q < 3; q++) {
        int idx = tid + q*TPASS;
        atomicMax(&g_mx[bi*CF + idx], __float_as_int(mx[q]));
        atomicMin(&g_mn[bi*CF + idx], __float_as_int(mn[q]));
        #pragma unroll
        for (int j = 0; j < 4; j++)
            sp4[idx*4 + j] = make_float4(S[q*16+4*j], S[q*16+4*j+1], S[q*16+4*j+2], S[q*16+4*j+3]);
    }
}

// ---------------- routing pass i>0: depth-3 pipeline; w + S in registers ----------------
__global__ __launch_bounds__(TPASS, 1)
void pass_kernel(const float* __restrict__ u) {
    extern __shared__ float sh[];
    float* ubuf  = sh;              // 3*SLICE
    float* c_sm  = sh + 3*SLICE;    // CF (raw dot, then c in-place)
    float* a_all = c_sm + CF;       // BCH*NF = 1152
    int bi = blockIdx.x / NCH, ch = blockIdx.x % NCH;
    int tid = threadIdx.x;
    int B0 = ch*BCH;

    int off[3], fi[3], idxq[3];
    #pragma unroll
    for (int q = 0; q < 3; q++) {
        int idx = tid + q*TPASS;
        int Ci = idx / NF; fi[q] = idx - Ci*NF;
        off[q] = Ci*(NP*NF) + fi[q];
        idxq[q] = idx;
    }

    // preload all 32 a-rows
    #pragma unroll
    for (int q = 0; q < 3; q++)
        a_all[tid + q*TPASS] = g_asm[(bi*BB + B0)*NF + tid + q*TPASS];

    // w registers: (C,f,p) layout -> 4 LDG.128 per pair
    float w[48];
    #pragma unroll
    for (int q = 0; q < 3; q++) {
        const float4* wp = (const float4*)(g_w + (size_t)bi*SLICE + idxq[q]*NP);
        #pragma unroll
        for (int j = 0; j < 4; j++) {
            float4 v4 = wp[j];
            w[q*16+4*j] = v4.x; w[q*16+4*j+1] = v4.y; w[q*16+4*j+2] = v4.z; w[q*16+4*j+3] = v4.w;
        }
    }

    float S[48];
    #pragma unroll
    for (int j = 0; j < 48; j++) S[j] = 0.f;

    // prologue: prefetch iters 0 and 1
    #pragma unroll
    for (int pi = 0; pi < 2; pi++) {
        const float4* up = (const float4*)(u + (size_t)(bi*BB + B0 + pi)*SLICE);
        float* dst = ubuf + pi*SLICE;
        #pragma unroll
        for (int k = 0; k < 12; k++) cp_async16(dst + 4*(tid + k*TPASS), up + tid + k*TPASS);
        cp_commit();
    }

    int bufc = 0, bufn = 2;
    for (int i = 0; i < BCH; i++) {
        __syncthreads();
        if (i + 2 < BCH) {
            const float4* up = (const float4*)(u + (size_t)(bi*BB + B0 + i + 2)*SLICE);
            float* dst = ubuf + bufn*SLICE;
            #pragma unroll
            for (int k = 0; k < 12; k++) cp_async16(dst + 4*(tid + k*TPASS), up + tid + k*TPASS);
        }
        cp_commit();
        cp_wait2();
        __syncthreads();

        const float* usm = ubuf + bufc*SLICE;
        // raw dot r[C,f] = sum_p u * w_pre   (w premultiplied by s)
        #pragma unroll
        for (int q = 0; q < 3; q++) {
            float acc = 0.f;
            #pragma unroll
            for (int p = 0; p < NP; p++)
                acc = fmaf(usm[off[q] + p*NF], w[q*16 + p], acc);
            c_sm[idxq[q]] = acc;
        }
        __syncthreads();
        // softmax over C per f (144 threads: 4 lanes/f, 8 C each)
        if (tid < 144) {
            unsigned mask = (tid < 128) ? 0xffffffffu : 0x0000ffffu;
            int f = tid >> 2, sub = tid & 3;
            float* col = c_sm + f;
            int base = sub * 8;
            float m = -1e30f;
            #pragma unroll
            for (int c = 0; c < 8; c++) m = fmaxf(m, col[(base + c)*NF]);
            m = fmaxf(m, __shfl_xor_sync(mask, m, 1, 4));
            m = fmaxf(m, __shfl_xor_sync(mask, m, 2, 4));
            float e[8]; float sum = 0.f;
            #pragma unroll
            for (int c = 0; c < 8; c++) { e[c] = __expf(col[(base + c)*NF] - m); sum += e[c]; }
            sum += __shfl_xor_sync(mask, sum, 1, 4);
            sum += __shfl_xor_sync(mask, sum, 2, 4);
            float sc = a_all[i*NF + f] * (float)NC / sum;
            #pragma unroll
            for (int c = 0; c < 8; c++) col[(base + c)*NF] = e[c] * sc;
        }
        __syncthreads();
        // S += c * u
        #pragma unroll
        for (int q = 0; q < 3; q++) {
            float cv = c_sm[idxq[q]];
            #pragma unroll
            for (int p = 0; p < NP; p++)
                S[q*16 + p] = fmaf(cv, usm[off[q] + p*NF], S[q*16 + p]);
        }
        bufc = (bufc + 1 == 3) ? 0 : bufc + 1;
        bufn = (bufn + 1 == 3) ? 0 : bufn + 1;
    }
    float4* sp4 = (float4*)(g_Spart + (size_t)(bi*NCH + ch)*SLICE);
    #pragma unroll
    for (int q = 0; q < 3; q++) {
        #pragma unroll
        for (int j = 0; j < 4; j++)
            sp4[idxq[q]*4 + j] = make_float4(S[q*16+4*j], S[q*16+4*j+1], S[q*16+4*j+2], S[q*16+4*j+3]);
    }
}

// ---------------- fused chunk-reduce + squash: float4 over p, 4-lane groups ----------------
template<int IT>
__global__ void v_kernel(float* __restrict__ out) {
    int t = blockIdx.x * blockDim.x + threadIdx.x;   // exactly NB*CF*4 threads
    int g = t >> 2, pq = t & 3;
    int bi = g / CF, idx = g - bi*CF;                // idx = Ci*NF + f

    const float4* sp = (const float4*)g_Spart + (size_t)bi*NCH*(SLICE/4) + idx*4 + pq;
    float4 acc = make_float4(0.f, 0.f, 0.f, 0.f);
    #pragma unroll
    for (int ch = 0; ch < NCH; ch++) {
        float4 v = sp[(size_t)ch*(SLICE/4)];
        acc.x += v.x; acc.y += v.y; acc.z += v.z; acc.w += v.w;
    }

    float s;
    if (IT == 0) {
        s = 1.f / (__int_as_float(g_mx[g]) - __int_as_float(g_mn[g]));
        if (pq == 0) g_s[g] = s;
    } else {
        s = g_s[g];
    }

    acc.x *= s; acc.y *= s; acc.z *= s; acc.w *= s;
    float sn = acc.x*acc.x + acc.y*acc.y + acc.z*acc.z + acc.w*acc.w;
    sn += __shfl_xor_sync(0xffffffffu, sn, 1, 4);
    sn += __shfl_xor_sync(0xffffffffu, sn, 2, 4);
    float fac = (sn / (1.f + sn)) * rsqrtf(sn + EPS);

    if (IT < 2) {
        float4* wp = (float4*)(g_w + (size_t)bi*SLICE + idx*NP) + pq;
        float sf = s * fac;
        float4 nv = make_float4(acc.x*sf, acc.y*sf, acc.z*sf, acc.w*sf);
        if (IT == 1) {
            float4 ow = wp[0];
            nv.x += ow.x; nv.y += ow.y; nv.z += ow.z; nv.w += ow.w;
        }
        wp[0] = nv;
    } else {
        int Ci = idx / NF, f = idx - Ci*NF;
        float* ob = out + ((size_t)(bi*NC + Ci)*NP + pq*4)*NF + f;
        ob[0]      = acc.x * fac;
        ob[NF]     = acc.y * fac;
        ob[2*NF]   = acc.z * fac;
        ob[3*NF]   = acc.w * fac;
        if (pq == 0) out[NB*SLICE + g] = sqrtf(sn) * fac;
    }
}

// ---------------- launch ----------------
extern "C" void kernel_launch(void* const* d_in, const int* in_sizes, int n_in,
                              void* d_out, int out_size) {
    const float* u = (const float*)d_in[0];
    const float* a = (const float*)d_in[1];
    if (n_in >= 2 && in_sizes[0] < in_sizes[1]) {
        u = (const float*)d_in[1];
        a = (const float*)d_in[0];
    }
    float* out = (float*)d_out;

    const int SMEM0 = (3*SLICE + BCH*NF) * sizeof(float);        // 225,792 B
    const int SMEM1 = (3*SLICE + CF + BCH*NF) * sizeof(float);   // 230,400 B
    cudaFuncSetAttribute(pass0_kernel, cudaFuncAttributeMaxDynamicSharedMemorySize, SMEM0);
    cudaFuncSetAttribute(pass_kernel,  cudaFuncAttributeMaxDynamicSharedMemorySize, SMEM1);

    const int GP = NB * NCH;               // 144 pass blocks (1/SM)
    const int GV = NB * CF * 4 / 256;      // 288 v blocks

    init_kernel<<<(NB*CF + 255)/256, 256>>>();
    asm_kernel<<<NB*NF, BB>>>(a);

    pass0_kernel<<<GP, TPASS, SMEM0>>>(u);
    v_kernel<0><<<GV, 256>>>(out);

    pass_kernel<<<GP, TPASS, SMEM1>>>(u);
    v_kernel<1><<<GV, 256>>>(out);

    pass_kernel<<<GP, TPASS, SMEM1>>>(u);
    v_kernel<2><<<GV, 256>>>(out);
}

// round 11
// speedup vs baseline: 1.9706x; 1.0624x over previous
#include <cuda_runtime.h>
#include <cstdint>

// Problem constants
#define NB 16        // batch
#define BB 288       // input capsules
#define NC 32        // output capsules (softmax dim)
#define NP 16        // pose dim
#define NF 36        // f*f positions
#define SLICE (NC*NP*NF)   // 18432 floats = one (b,B) slice
#define CF (NC*NF)         // 1152
#define NCH 9              // B chunks
#define BCH 32             // B per chunk
#define TPASS 384          // pass threads: 1152/384 = 3 (C,f) pairs each
#define EPS 1e-5f

// ---------------- device scratch (~12.7 MB) ----------------
__device__ float g_asm[NB*BB*NF];                 // softmax_B(a)
__device__ float g_Spart[(size_t)NB*NCH*SLICE];   // partial S, (C,f,p) layout per (b,ch)
__device__ float g_w[NB*SLICE];                   // s-premultiplied running sum of v, (C,f,p)
__device__ float g_s[NB*CF];                      // 1/(mx-mn)
__device__ int   g_mx[NB*CF];
__device__ int   g_mn[NB*CF];

// ---------------- cp.async helpers ----------------
__device__ __forceinline__ void cp_async16(float* smem_ptr, const float4* gptr) {
    uint32_t sa = (uint32_t)__cvta_generic_to_shared(smem_ptr);
    asm volatile("cp.async.cg.shared.global [%0], [%1], 16;" :: "r"(sa), "l"(gptr));
}
__device__ __forceinline__ void cp_commit() { asm volatile("cp.async.commit_group;"); }
__device__ __forceinline__ void cp_wait2()  { asm volatile("cp.async.wait_group 2;" ::: "memory"); }

// ---------------- init ----------------
__global__ void init_kernel() {
    int g = blockIdx.x * blockDim.x + threadIdx.x;
    if (g < NB*CF) { g_mx[g] = 0; g_mn[g] = 0x7F800000; }
}

// ---------------- softmax of a over B, per (b,f) ----------------
__global__ void asm_kernel(const float* __restrict__ a) {
    __shared__ float red[BB];
    int bf = blockIdx.x;
    int bi = bf / NF, f = bf - bi*NF;
    int t = threadIdx.x;
    float x = a[(bi*BB + t)*NF + f];
    red[t] = x; __syncthreads();
    for (int st = 256; st >= 1; st >>= 1) {
        if (t < st && t + st < BB) red[t] = fmaxf(red[t], red[t + st]);
        __syncthreads();
    }
    float m = red[0]; __syncthreads();
    float e = __expf(x - m);
    red[t] = e; __syncthreads();
    for (int st = 256; st >= 1; st >>= 1) {
        if (t < st && t + st < BB) red[t] += red[t + st];
        __syncthreads();
    }
    g_asm[(bi*BB + t)*NF + f] = e / red[0];
}

// ---------------- pass 0: depth-3 pipeline; norms + S0 from registers ----------------
__global__ __launch_bounds__(TPASS, 1)
void pass0_kernel(const float* __restrict__ u) {
    extern __shared__ float sh[];
    float* ubuf  = sh;              // 3*SLICE triple buffer
    float* a_all = sh + 3*SLICE;    // BCH*NF = 1152 (all a-rows for this chunk)
    int bi = blockIdx.x / NCH, ch = blockIdx.x % NCH;
    int tid = threadIdx.x;
    int B0 = ch*BCH;

    int off[3], fi[3];
    #pragma unroll
    for (int q = 0; q < 3; q++) {
        int idx = tid + q*TPASS;          // < 1152
        int Ci = idx / NF; fi[q] = idx - Ci*NF;
        off[q] = Ci*(NP*NF) + fi[q];      // + p*NF strides
    }

    // preload all 32 a-rows (contiguous)
    #pragma unroll
    for (int q = 0; q < 3; q++)
        a_all[tid + q*TPASS] = g_asm[(bi*BB + B0)*NF + tid + q*TPASS];

    float S[48];
    #pragma unroll
    for (int j = 0; j < 48; j++) S[j] = 0.f;
    float mx[3] = {-1e30f, -1e30f, -1e30f};
    float mn[3] = { 1e30f,  1e30f,  1e30f};

    // prologue: prefetch iters 0 and 1
    #pragma unroll
    for (int pi = 0; pi < 2; pi++) {
        const float4* up = (const float4*)(u + (size_t)(bi*BB + B0 + pi)*SLICE);
        float* dst = ubuf + pi*SLICE;
        #pragma unroll
        for (int k = 0; k < 12; k++) cp_async16(dst + 4*(tid + k*TPASS), up + tid + k*TPASS);
        cp_commit();
    }

    int bufc = 0;   // buffer of iter i
    int bufn = 2;   // buffer receiving iter i+2
    for (int i = 0; i < BCH; i++) {
        __syncthreads();                              // compute i-1 done; bufn free
        if (i + 2 < BCH) {
            const float4* up = (const float4*)(u + (size_t)(bi*BB + B0 + i + 2)*SLICE);
            float* dst = ubuf + bufn*SLICE;
            #pragma unroll
            for (int k = 0; k < 12; k++) cp_async16(dst + 4*(tid + k*TPASS), up + tid + k*TPASS);
        }
        cp_commit();                                  // empty group ok at tail
        cp_wait2();                                   // group i complete
        __syncthreads();                              // buffer i visible

        const float* usm = ubuf + bufc*SLICE;
        const float* ar = a_all + i*NF;
        #pragma unroll
        for (int q = 0; q < 3; q++) {
            float aw = ar[fi[q]];
            float nrm = 0.f;
            #pragma unroll
            for (int p = 0; p < NP; p++) {
                float x = usm[off[q] + p*NF];
                nrm = fmaf(x, x, nrm);
                S[q*16 + p] = fmaf(aw, x, S[q*16 + p]);
            }
            float nr = sqrtf(nrm);
            mx[q] = fmaxf(mx[q], nr);
            mn[q] = fminf(mn[q], nr);
        }
        bufc = (bufc + 1 == 3) ? 0 : bufc + 1;
        bufn = (bufn + 1 == 3) ? 0 : bufn + 1;
    }
    // min/max atomics + coalesced (C,f,p) partial-S writeback
    float4* sp4 = (float4*)(g_Spart + (size_t)(bi*NCH + ch)*SLICE);
    #pragma unroll
    for (int q = 0; q < 3; q++) {
        int idx = tid + q*TPASS;
        atomicMax(&g_mx[bi*CF + idx], __float_as_int(mx[q]));
        atomicMin(&g_mn[bi*CF + idx], __float_as_int(mn[q]));
        #pragma unroll
        for (int j = 0; j < 4; j++)
            sp4[idx*4 + j] = make_float4(S[q*16+4*j], S[q*16+4*j+1], S[q*16+4*j+2], S[q*16+4*j+3]);
    }
}

// ---------------- routing pass i>0: u cached in registers across softmax ----------------
__global__ __launch_bounds__(TPASS, 1)
void pass_kernel(const float* __restrict__ u) {
    extern __shared__ float sh[];
    float* ubuf  = sh;              // 3*SLICE
    float* c_sm  = sh + 3*SLICE;    // CF (raw dot, then c in-place)
    float* a_all = c_sm + CF;       // BCH*NF = 1152
    int bi = blockIdx.x / NCH, ch = blockIdx.x % NCH;
    int tid = threadIdx.x;
    int B0 = ch*BCH;

    int off[3], idxq[3];
    #pragma unroll
    for (int q = 0; q < 3; q++) {
        int idx = tid + q*TPASS;
        int Ci = idx / NF;
        off[q] = Ci*(NP*NF) + (idx - Ci*NF);
        idxq[q] = idx;
    }

    // preload all 32 a-rows
    #pragma unroll
    for (int q = 0; q < 3; q++)
        a_all[tid + q*TPASS] = g_asm[(bi*BB + B0)*NF + tid + q*TPASS];

    // w registers: (C,f,p) layout -> 4 LDG.128 per pair
    float w[48];
    #pragma unroll
    for (int q = 0; q < 3; q++) {
        const float4* wp = (const float4*)(g_w + (size_t)bi*SLICE + idxq[q]*NP);
        #pragma unroll
        for (int j = 0; j < 4; j++) {
            float4 v4 = wp[j];
            w[q*16+4*j] = v4.x; w[q*16+4*j+1] = v4.y; w[q*16+4*j+2] = v4.z; w[q*16+4*j+3] = v4.w;
        }
    }

    float S[48];
    #pragma unroll
    for (int j = 0; j < 48; j++) S[j] = 0.f;

    // prologue: prefetch iters 0 and 1
    #pragma unroll
    for (int pi = 0; pi < 2; pi++) {
        const float4* up = (const float4*)(u + (size_t)(bi*BB + B0 + pi)*SLICE);
        float* dst = ubuf + pi*SLICE;
        #pragma unroll
        for (int k = 0; k < 12; k++) cp_async16(dst + 4*(tid + k*TPASS), up + tid + k*TPASS);
        cp_commit();
    }

    int bufc = 0, bufn = 2;
    for (int i = 0; i < BCH; i++) {
        __syncthreads();
        if (i + 2 < BCH) {
            const float4* up = (const float4*)(u + (size_t)(bi*BB + B0 + i + 2)*SLICE);
            float* dst = ubuf + bufn*SLICE;
            #pragma unroll
            for (int k = 0; k < 12; k++) cp_async16(dst + 4*(tid + k*TPASS), up + tid + k*TPASS);
        }
        cp_commit();
        cp_wait2();
        __syncthreads();

        const float* usm = ubuf + bufc*SLICE;
        // dot phase: read u ONCE into registers, dot with w
        float ur[48];
        #pragma unroll
        for (int q = 0; q < 3; q++) {
            float acc = 0.f;
            #pragma unroll
            for (int p = 0; p < NP; p++) {
                float x = usm[off[q] + p*NF];
                ur[q*16 + p] = x;
                acc = fmaf(x, w[q*16 + p], acc);
            }
            c_sm[idxq[q]] = acc;
        }
        __syncthreads();
        // softmax over C per f (144 threads: 4 lanes/f, 8 C each)
        if (tid < 144) {
            unsigned mask = (tid < 128) ? 0xffffffffu : 0x0000ffffu;
            int f = tid >> 2, sub = tid & 3;
            float* col = c_sm + f;
            int base = sub * 8;
            float m = -1e30f;
            #pragma unroll
            for (int c = 0; c < 8; c++) m = fmaxf(m, col[(base + c)*NF]);
            m = fmaxf(m, __shfl_xor_sync(mask, m, 1, 4));
            m = fmaxf(m, __shfl_xor_sync(mask, m, 2, 4));
            float e[8]; float sum = 0.f;
            #pragma unroll
            for (int c = 0; c < 8; c++) { e[c] = __expf(col[(base + c)*NF] - m); sum += e[c]; }
            sum += __shfl_xor_sync(mask, sum, 1, 4);
            sum += __shfl_xor_sync(mask, sum, 2, 4);
            float sc = a_all[i*NF + f] * (float)NC / sum;
            #pragma unroll
            for (int c = 0; c < 8; c++) col[(base + c)*NF] = e[c] * sc;
        }
        __syncthreads();
        // S += c * u   (u from registers — no smem re-read)
        #pragma unroll
        for (int q = 0; q < 3; q++) {
            float cv = c_sm[idxq[q]];
            #pragma unroll
            for (int p = 0; p < NP; p++)
                S[q*16 + p] = fmaf(cv, ur[q*16 + p], S[q*16 + p]);
        }
        bufc = (bufc + 1 == 3) ? 0 : bufc + 1;
        bufn = (bufn + 1 == 3) ? 0 : bufn + 1;
    }
    float4* sp4 = (float4*)(g_Spart + (size_t)(bi*NCH + ch)*SLICE);
    #pragma unroll
    for (int q = 0; q < 3; q++) {
        #pragma unroll
        for (int j = 0; j < 4; j++)
            sp4[idxq[q]*4 + j] = make_float4(S[q*16+4*j], S[q*16+4*j+1], S[q*16+4*j+2], S[q*16+4*j+3]);
    }
}

// ---------------- fused chunk-reduce + squash: 8 threads/(b,C,f), chunk-split ----------------
template<int IT>
__global__ void v_kernel(float* __restrict__ out) {
    int t = blockIdx.x * blockDim.x + threadIdx.x;   // exactly NB*CF*8 threads
    int g = t >> 3, sub = t & 7;
    int pq = sub & 3, h = sub >> 2;
    int bi = g / CF, idx = g - bi*CF;                // idx = Ci*NF + f

    const float4* sp = (const float4*)g_Spart + (size_t)bi*NCH*(SLICE/4) + idx*4 + pq;
    float4 acc = make_float4(0.f, 0.f, 0.f, 0.f);
    int c0 = h ? 5 : 0, c1 = h ? NCH : 5;
    for (int ch = c0; ch < c1; ch++) {
        float4 v = sp[(size_t)ch*(SLICE/4)];
        acc.x += v.x; acc.y += v.y; acc.z += v.z; acc.w += v.w;
    }
    // merge the two chunk-halves (lanes h=0/1, same pq)
    acc.x += __shfl_xor_sync(0xffffffffu, acc.x, 4, 8);
    acc.y += __shfl_xor_sync(0xffffffffu, acc.y, 4, 8);
    acc.z += __shfl_xor_sync(0xffffffffu, acc.z, 4, 8);
    acc.w += __shfl_xor_sync(0xffffffffu, acc.w, 4, 8);

    float s;
    if (IT == 0) {
        s = 1.f / (__int_as_float(g_mx[g]) - __int_as_float(g_mn[g]));
        if (sub == 0) g_s[g] = s;
    } else {
        s = g_s[g];
    }

    acc.x *= s; acc.y *= s; acc.z *= s; acc.w *= s;
    float sn = acc.x*acc.x + acc.y*acc.y + acc.z*acc.z + acc.w*acc.w;
    sn += __shfl_xor_sync(0xffffffffu, sn, 1, 4);
    sn += __shfl_xor_sync(0xffffffffu, sn, 2, 4);
    float fac = (sn / (1.f + sn)) * rsqrtf(sn + EPS);

    if (IT < 2) {
        if (h == 0) {
            float4* wp = (float4*)(g_w + (size_t)bi*SLICE + idx*NP) + pq;
            float sf = s * fac;
            float4 nv = make_float4(acc.x*sf, acc.y*sf, acc.z*sf, acc.w*sf);
            if (IT == 1) {
                float4 ow = wp[0];
                nv.x += ow.x; nv.y += ow.y; nv.z += ow.z; nv.w += ow.w;
            }
            wp[0] = nv;
        }
    } else {
        if (h == 0) {
            int Ci = idx / NF, f = idx - Ci*NF;
            float* ob = out + ((size_t)(bi*NC + Ci)*NP + pq*4)*NF + f;
            ob[0]      = acc.x * fac;
            ob[NF]     = acc.y * fac;
            ob[2*NF]   = acc.z * fac;
            ob[3*NF]   = acc.w * fac;
            if (pq == 0) out[NB*SLICE + g] = sqrtf(sn) * fac;
        }
    }
}

// ---------------- launch ----------------
extern "C" void kernel_launch(void* const* d_in, const int* in_sizes, int n_in,
                              void* d_out, int out_size) {
    const float* u = (const float*)d_in[0];
    const float* a = (const float*)d_in[1];
    if (n_in >= 2 && in_sizes[0] < in_sizes[1]) {
        u = (const float*)d_in[1];
        a = (const float*)d_in[0];
    }
    float* out = (float*)d_out;

    const int SMEM0 = (3*SLICE + BCH*NF) * sizeof(float);        // 225,792 B
    const int SMEM1 = (3*SLICE + CF + BCH*NF) * sizeof(float);   // 230,400 B
    cudaFuncSetAttribute(pass0_kernel, cudaFuncAttributeMaxDynamicSharedMemorySize, SMEM0);
    cudaFuncSetAttribute(pass_kernel,  cudaFuncAttributeMaxDynamicSharedMemorySize, SMEM1);

    const int GP = NB * NCH;               // 144 pass blocks (1/SM)
    const int GV = NB * CF * 8 / 256;      // 576 v blocks

    init_kernel<<<(NB*CF + 255)/256, 256>>>();
    asm_kernel<<<NB*NF, BB>>>(a);

    pass0_kernel<<<GP, TPASS, SMEM0>>>(u);
    v_kernel<0><<<GV, 256>>>(out);

    pass_kernel<<<GP, TPASS, SMEM1>>>(u);
    v_kernel<1><<<GV, 256>>>(out);

    pass_kernel<<<GP, TPASS, SMEM1>>>(u);
    v_kernel<2><<<GV, 256>>>(out);
}